// round 1
// baseline (speedup 1.0000x reference)
#include <cuda_runtime.h>
#include <cuda_bf16.h>
#include <math.h>

// ---------------- problem constants ----------------
#define NB     256
#define CC     128
#define HH     77
#define WW     44
#define PP     7
#define MAXH   11
#define POSEC  256
#define VV     17
#define OUTC   512
#define DEPTH  4
#define HEADS  8
#define DHEAD  64
#define FFH    1024
#define FUSED  1920          // C*MAX_H + POSE_C*2 = 1408 + 512
#define TOK    (NB*PP)       // 1792

// ---------------- scratch (static device memory; no allocation) ----------------
__device__ float g_X0[TOK * FUSED];     // fused features (pre-LN0)
__device__ float g_Xn[TOK * FUSED];     // LN outputs (reused, packed per-D)
__device__ float g_fuse[TOK * OUTC];    // residual stream
__device__ float g_qkv[TOK * 3 * OUTC];
__device__ float g_ao[TOK * OUTC];      // attention output
__device__ float g_ff[TOK * FFH];

// ---------------- 1) silhouette pooling: mean+max over W per (n,p,c,hl) ----------------
__global__ void pool_kernel(const float* __restrict__ sil, const int* __restrict__ mins,
                            float* __restrict__ X0) {
    int idx = blockIdx.x * blockDim.x + threadIdx.x;
    const int total = NB * PP * CC * MAXH;
    if (idx >= total) return;
    int hl = idx % MAXH;
    int c  = (idx / MAXH) % CC;
    int p  = (idx / (MAXH * CC)) % PP;
    int n  = idx / (MAXH * CC * PP);
    int start = mins[p * NB + n];
    start = min(max(start, 0), HH - MAXH);   // dynamic_slice clamp semantics
    int h = start + hl;
    const float4* row = (const float4*)(sil + (((size_t)n * CC + c) * HH + h) * WW);
    float s = 0.0f, mx = -3.4e38f;
#pragma unroll
    for (int w = 0; w < WW / 4; w++) {
        float4 v = row[w];
        s += v.x + v.y + v.z + v.w;
        mx = fmaxf(mx, fmaxf(fmaxf(v.x, v.y), fmaxf(v.z, v.w)));
    }
    X0[((size_t)(n * PP + p)) * FUSED + c * MAXH + hl] = s * (1.0f / WW) + mx;
}

// ---------------- 2) pose binning + leaky relu ----------------
__global__ void pose_kernel(const float* __restrict__ pose, float* __restrict__ X0) {
    int idx = blockIdx.x * blockDim.x + threadIdx.x;
    const int total = NB * PP * POSEC * 2;
    if (idx >= total) return;
    int b  = idx & 1;
    int pc = (idx >> 1) & (POSEC - 1);
    int p  = (idx >> 9) % PP;
    int n  = idx / (PP * POSEC * 2);
    const float* pp = pose + ((size_t)n * POSEC + pc) * VV;
    float v;
    if (p == 0) {
        // group [0,1,2,3,4]: bin0 = mean(cols 0..2), bin1 = mean(cols 2..4)
        v = (b == 0) ? (pp[0] + pp[1] + pp[2]) * (1.0f / 3.0f)
                     : (pp[2] + pp[3] + pp[4]) * (1.0f / 3.0f);
    } else {
        // groups [5,6],[7,8],...: bin b = single column 3 + 2p + b
        v = pp[3 + 2 * p + b];
    }
    v = (v >= 0.0f) ? v : 0.01f * v;   // leaky_relu(0.01)
    X0[((size_t)(n * PP + p)) * FUSED + CC * MAXH + pc * 2 + b] = v;
}

// ---------------- 3) LayerNorm (block per row) ----------------
template <int D>
__global__ void ln_kernel(const float* __restrict__ X, float* __restrict__ Y,
                          const float* __restrict__ g, const float* __restrict__ b) {
    constexpr int NT = 256;
    constexpr int NE = (D + NT - 1) / NT;
    int row = blockIdx.x;
    const float* x = X + (size_t)row * D;
    float* y = Y + (size_t)row * D;
    int t = threadIdx.x;
    float vals[NE];
    float s = 0.0f, s2 = 0.0f;
#pragma unroll
    for (int e = 0; e < NE; e++) {
        int i = t + e * NT;
        float v = (i < D) ? x[i] : 0.0f;
        vals[e] = v;
        s += v; s2 += v * v;
    }
#pragma unroll
    for (int o = 16; o > 0; o >>= 1) {
        s  += __shfl_xor_sync(0xFFFFFFFFu, s, o);
        s2 += __shfl_xor_sync(0xFFFFFFFFu, s2, o);
    }
    __shared__ float sh[20];
    int wid = t >> 5, lid = t & 31;
    if (lid == 0) { sh[wid] = s; sh[8 + wid] = s2; }
    __syncthreads();
    if (t == 0) {
        float ts = 0.0f, ts2 = 0.0f;
#pragma unroll
        for (int w = 0; w < NT / 32; w++) { ts += sh[w]; ts2 += sh[8 + w]; }
        float m = ts / D;
        float var = ts2 / D - m * m;
        sh[16] = m;
        sh[17] = rsqrtf(var + 1e-5f);
    }
    __syncthreads();
    float m = sh[16], r = sh[17];
#pragma unroll
    for (int e = 0; e < NE; e++) {
        int i = t + e * NT;
        if (i < D) y[i] = (vals[e] - m) * r * g[i] + b[i];
    }
}

// ---------------- 4) fp32 GEMM, 64x64x16 tiles, 4x4 micro, fused epilogue ----------------
// C[M,N] = epilogue(A[M,K] @ B[K,N]). All of M,N % 64 == 0 and K % 16 == 0 (checked statically
// for this problem), so no bounds checks.
template <bool BIAS, bool RES, bool GELU>
__global__ void gemm_kernel(const float* __restrict__ A, const float* __restrict__ B,
                            const float* __restrict__ bias, const float* __restrict__ Res,
                            float* __restrict__ C, int M, int Nn, int K) {
    constexpr int BM = 64, BN = 64, BK = 16;
    __shared__ float As[BK][BM];
    __shared__ float Bs[BK][BN];
    int tid = threadIdx.x;                 // 256 threads
    int bm = blockIdx.y * BM;
    int bn = blockIdx.x * BN;
    int tx = tid & 15, ty = tid >> 4;

    float acc[4][4] = {};

    int arow = tid >> 2;                   // 0..63
    int akq  = (tid & 3) * 4;              // 0,4,8,12
    int brow = tid >> 4;                   // 0..15
    int bnq  = (tid & 15) * 4;             // 0..60

    const float* Aptr = A + (size_t)(bm + arow) * K + akq;
    const float* Bptr = B + (size_t)brow * Nn + bn + bnq;

    for (int k0 = 0; k0 < K; k0 += BK) {
        float4 av = *(const float4*)(Aptr + k0);
        float4 bv = *(const float4*)(Bptr + (size_t)k0 * Nn);
        As[akq + 0][arow] = av.x;
        As[akq + 1][arow] = av.y;
        As[akq + 2][arow] = av.z;
        As[akq + 3][arow] = av.w;
        *(float4*)&Bs[brow][bnq] = bv;
        __syncthreads();
#pragma unroll
        for (int k = 0; k < BK; k++) {
            float4 a = *(const float4*)&As[k][ty * 4];
            float4 b = *(const float4*)&Bs[k][tx * 4];
            float ar[4] = {a.x, a.y, a.z, a.w};
            float br[4] = {b.x, b.y, b.z, b.w};
#pragma unroll
            for (int i = 0; i < 4; i++)
#pragma unroll
                for (int j = 0; j < 4; j++)
                    acc[i][j] += ar[i] * br[j];
        }
        __syncthreads();
    }

#pragma unroll
    for (int i = 0; i < 4; i++) {
        int row = bm + ty * 4 + i;
        float* crow = C + (size_t)row * Nn + bn + tx * 4;
        const float* rrow = RES ? (Res + (size_t)row * Nn + bn + tx * 4) : nullptr;
        float4 o;
        float vv[4];
#pragma unroll
        for (int j = 0; j < 4; j++) {
            float v = acc[i][j];
            if (BIAS) v += bias[bn + tx * 4 + j];
            if (GELU) v = v * 0.5f * (1.0f + erff(v * 0.70710678118654752f));
            if (RES)  v += rrow[j];
            vv[j] = v;
        }
        o.x = vv[0]; o.y = vv[1]; o.z = vv[2]; o.w = vv[3];
        *(float4*)crow = o;
    }
}

// ---------------- 5) attention: one block per (n, head), P=7 tokens ----------------
__global__ void attn_kernel(const float* __restrict__ qkv, float* __restrict__ out) {
    int nb = blockIdx.x;                 // n*HEADS + h
    int n = nb / HEADS, h = nb % HEADS;
    __shared__ float q[PP][DHEAD + 1];
    __shared__ float k[PP][DHEAD + 1];
    __shared__ float v[PP][DHEAD + 1];
    __shared__ float pr[PP][PP + 1];
    int t = threadIdx.x;                 // 64 threads
#pragma unroll
    for (int i = 0; i < PP; i++) {
        const float* base = qkv + (size_t)(n * PP + i) * (3 * OUTC) + h * DHEAD;
        q[i][t] = base[t];
        k[i][t] = base[OUTC + t];
        v[i][t] = base[2 * OUTC + t];
    }
    __syncthreads();
    if (t < PP * PP) {
        int i = t / PP, j = t % PP;
        float s = 0.0f;
#pragma unroll
        for (int d = 0; d < DHEAD; d++) s += q[i][d] * k[j][d];
        pr[i][j] = s * 0.125f;           // DHEAD^-0.5
    }
    __syncthreads();
    if (t < PP) {
        float mx = -3.4e38f;
#pragma unroll
        for (int j = 0; j < PP; j++) mx = fmaxf(mx, pr[t][j]);
        float sm = 0.0f;
#pragma unroll
        for (int j = 0; j < PP; j++) { float e = expf(pr[t][j] - mx); pr[t][j] = e; sm += e; }
        float inv = 1.0f / sm;
#pragma unroll
        for (int j = 0; j < PP; j++) pr[t][j] *= inv;
    }
    __syncthreads();
#pragma unroll
    for (int i = 0; i < PP; i++) {
        float o = 0.0f;
#pragma unroll
        for (int j = 0; j < PP; j++) o += pr[i][j] * v[j][t];
        out[(size_t)(n * PP + i) * OUTC + h * DHEAD + t] = o;
    }
}

// ---------------- launcher ----------------
extern "C" void kernel_launch(void* const* d_in, const int* in_sizes, int n_in,
                              void* d_out, int out_size) {
    const float* sil    = (const float*)d_in[0];
    const float* pose   = (const float*)d_in[1];
    const int*   mins   = (const int*)  d_in[2];
    // d_in[3] = maxs (unused)
    const float* ln0_g  = (const float*)d_in[4];
    const float* ln0_b  = (const float*)d_in[5];
    const float* We     = (const float*)d_in[6];
    const float* be     = (const float*)d_in[7];
    const float* ln1_g  = (const float*)d_in[8];
    const float* ln1_b  = (const float*)d_in[9];
    const float* ln_a_g = (const float*)d_in[10];
    const float* ln_a_b = (const float*)d_in[11];
    const float* Wqkv   = (const float*)d_in[12];
    const float* Wo     = (const float*)d_in[13];
    const float* bo     = (const float*)d_in[14];
    const float* ln_f_g = (const float*)d_in[15];
    const float* ln_f_b = (const float*)d_in[16];
    const float* W1     = (const float*)d_in[17];
    const float* b1     = (const float*)d_in[18];
    const float* W2     = (const float*)d_in[19];
    const float* b2     = (const float*)d_in[20];
    float* out = (float*)d_out;

    float *X0, *Xn, *fuse, *qkv, *ao, *ff;
    cudaGetSymbolAddress((void**)&X0,   g_X0);
    cudaGetSymbolAddress((void**)&Xn,   g_Xn);
    cudaGetSymbolAddress((void**)&fuse, g_fuse);
    cudaGetSymbolAddress((void**)&qkv,  g_qkv);
    cudaGetSymbolAddress((void**)&ao,   g_ao);
    cudaGetSymbolAddress((void**)&ff,   g_ff);

    // Stage 1: fuse features
    {
        int tot = NB * PP * CC * MAXH;
        pool_kernel<<<(tot + 255) / 256, 256>>>(sil, mins, X0);
    }
    {
        int tot = NB * PP * POSEC * 2;
        pose_kernel<<<(tot + 255) / 256, 256>>>(pose, X0);
    }

    // Stage 2: LN0 -> embed GEMM -> LN1
    ln_kernel<FUSED><<<TOK, 256>>>(X0, Xn, ln0_g, ln0_b);
    gemm_kernel<true, false, false><<<dim3(OUTC / 64, TOK / 64), 256>>>(
        Xn, We, be, nullptr, fuse, TOK, OUTC, FUSED);
    ln_kernel<OUTC><<<TOK, 256>>>(fuse, fuse, ln1_g, ln1_b);

    // Stage 3: transformer layers
    for (int l = 0; l < DEPTH; l++) {
        ln_kernel<OUTC><<<TOK, 256>>>(fuse, Xn, ln_a_g + l * OUTC, ln_a_b + l * OUTC);
        gemm_kernel<false, false, false><<<dim3(3 * OUTC / 64, TOK / 64), 256>>>(
            Xn, Wqkv + (size_t)l * OUTC * 3 * OUTC, nullptr, nullptr, qkv,
            TOK, 3 * OUTC, OUTC);
        attn_kernel<<<NB * HEADS, 64>>>(qkv, ao);
        gemm_kernel<true, true, false><<<dim3(OUTC / 64, TOK / 64), 256>>>(
            ao, Wo + (size_t)l * OUTC * OUTC, bo + l * OUTC, fuse, fuse,
            TOK, OUTC, OUTC);
        ln_kernel<OUTC><<<TOK, 256>>>(fuse, Xn, ln_f_g + l * OUTC, ln_f_b + l * OUTC);
        gemm_kernel<true, false, true><<<dim3(FFH / 64, TOK / 64), 256>>>(
            Xn, W1 + (size_t)l * OUTC * FFH, b1 + l * FFH, nullptr, ff,
            TOK, FFH, OUTC);
        float* outp = (l == DEPTH - 1) ? out : fuse;
        gemm_kernel<true, true, false><<<dim3(OUTC / 64, TOK / 64), 256>>>(
            ff, W2 + (size_t)l * FFH * OUTC, b2 + l * OUTC, fuse, outp,
            TOK, OUTC, FFH);
    }
}

// round 4
// speedup vs baseline: 1.5592x; 1.5592x over previous
#include <cuda_runtime.h>
#include <cuda_bf16.h>
#include <math.h>
#include <stdint.h>

// ---------------- problem constants ----------------
#define NB     256
#define CC     128
#define HH     77
#define WW     44
#define PP     7
#define MAXH   11
#define POSEC  256
#define VV     17
#define OUTC   512
#define DEPTH  4
#define HEADS  8
#define DHEAD  64
#define FFH    1024
#define FUSED  1920          // C*MAX_H + POSE_C*2 = 1408 + 512
#define TOK    (NB*PP)       // 1792

// ---------------- scratch (static device memory; no allocation) ----------------
__device__ float g_X0[TOK * FUSED];     // fused features (pre-LN0)
__device__ float g_Xn[TOK * FUSED];     // LN outputs
__device__ float g_fuse[TOK * OUTC];    // residual stream
__device__ float g_qkv[TOK * 3 * OUTC];
__device__ float g_ao[TOK * OUTC];      // attention output
__device__ float g_ff[TOK * FFH];

// ---------------- 1) silhouette pooling ----------------
__global__ void pool_kernel(const float* __restrict__ sil, const int* __restrict__ mins,
                            float* __restrict__ X0) {
    int idx = blockIdx.x * blockDim.x + threadIdx.x;
    const int total = NB * PP * CC * MAXH;
    if (idx >= total) return;
    int hl = idx % MAXH;
    int c  = (idx / MAXH) % CC;
    int p  = (idx / (MAXH * CC)) % PP;
    int n  = idx / (MAXH * CC * PP);
    int start = mins[p * NB + n];
    start = min(max(start, 0), HH - MAXH);
    int h = start + hl;
    const float4* row = (const float4*)(sil + (((size_t)n * CC + c) * HH + h) * WW);
    float s = 0.0f, mx = -3.4e38f;
#pragma unroll
    for (int w = 0; w < WW / 4; w++) {
        float4 v = row[w];
        s += v.x + v.y + v.z + v.w;
        mx = fmaxf(mx, fmaxf(fmaxf(v.x, v.y), fmaxf(v.z, v.w)));
    }
    X0[((size_t)(n * PP + p)) * FUSED + c * MAXH + hl] = s * (1.0f / WW) + mx;
}

// ---------------- 2) pose binning + leaky relu ----------------
__global__ void pose_kernel(const float* __restrict__ pose, float* __restrict__ X0) {
    int idx = blockIdx.x * blockDim.x + threadIdx.x;
    const int total = NB * PP * POSEC * 2;
    if (idx >= total) return;
    int b  = idx & 1;
    int pc = (idx >> 1) & (POSEC - 1);
    int p  = (idx >> 9) % PP;
    int n  = idx / (PP * POSEC * 2);
    const float* pp = pose + ((size_t)n * POSEC + pc) * VV;
    float v;
    if (p == 0) {
        v = (b == 0) ? (pp[0] + pp[1] + pp[2]) * (1.0f / 3.0f)
                     : (pp[2] + pp[3] + pp[4]) * (1.0f / 3.0f);
    } else {
        v = pp[3 + 2 * p + b];
    }
    v = (v >= 0.0f) ? v : 0.01f * v;
    X0[((size_t)(n * PP + p)) * FUSED + CC * MAXH + pc * 2 + b] = v;
}

// ---------------- 3) LayerNorm (block per row) ----------------
template <int D>
__global__ void ln_kernel(const float* __restrict__ X, float* __restrict__ Y,
                          const float* __restrict__ g, const float* __restrict__ b) {
    constexpr int NT = 256;
    constexpr int NE = (D + NT - 1) / NT;
    int row = blockIdx.x;
    const float* x = X + (size_t)row * D;
    float* y = Y + (size_t)row * D;
    int t = threadIdx.x;
    float vals[NE];
    float s = 0.0f, s2 = 0.0f;
#pragma unroll
    for (int e = 0; e < NE; e++) {
        int i = t + e * NT;
        float v = (i < D) ? x[i] : 0.0f;
        vals[e] = v;
        s += v; s2 += v * v;
    }
#pragma unroll
    for (int o = 16; o > 0; o >>= 1) {
        s  += __shfl_xor_sync(0xFFFFFFFFu, s, o);
        s2 += __shfl_xor_sync(0xFFFFFFFFu, s2, o);
    }
    __shared__ float sh[20];
    int wid = t >> 5, lid = t & 31;
    if (lid == 0) { sh[wid] = s; sh[8 + wid] = s2; }
    __syncthreads();
    if (t == 0) {
        float ts = 0.0f, ts2 = 0.0f;
#pragma unroll
        for (int w = 0; w < NT / 32; w++) { ts += sh[w]; ts2 += sh[8 + w]; }
        float m = ts / D;
        float var = ts2 / D - m * m;
        sh[16] = m;
        sh[17] = rsqrtf(var + 1e-5f);
    }
    __syncthreads();
    float m = sh[16], r = sh[17];
#pragma unroll
    for (int e = 0; e < NE; e++) {
        int i = t + e * NT;
        if (i < D) y[i] = (vals[e] - m) * r * g[i] + b[i];
    }
}

// ---------------- 4) tf32 tensor-core GEMM (mma.sync m16n8k8) ----------------
// Tile: BM=128, BN=64, BK=16. 8 warps (4 along M x 2 along N), warp tile 32x32.
// Double-buffered smem, cvt.rna.tf32 on the load path, fused epilogue.
// Requires M%128==0, N%64==0, K%16==0 (true for all calls here).
#define BMg 128
#define BNg 64
#define BKg 16

__device__ __forceinline__ uint32_t f2tf32(float f) {
    uint32_t u;
    asm("cvt.rna.tf32.f32 %0, %1;" : "=r"(u) : "f"(f));
    return u;
}

template <bool BIAS, bool RES, bool GELU>
__global__ __launch_bounds__(256, 2)
void gemm_tf32(const float* __restrict__ A, const float* __restrict__ B,
               const float* __restrict__ bias, const float* __restrict__ Res,
               float* __restrict__ C, int M, int Nn, int K) {
    __shared__ uint32_t As[2][BMg][BKg + 4];   // stride 20: fragment reads conflict-free
    __shared__ uint32_t Bs[2][BKg][BNg + 4];   // stride 68: fragment reads conflict-free

    int tid = threadIdx.x;
    int bm = blockIdx.y * BMg, bn = blockIdx.x * BNg;
    int w = tid >> 5, lane = tid & 31;
    int wm = (w & 3) * 32, wn = (w >> 2) * 32;
    int r = lane >> 2, cq = lane & 3;

    float acc[2][4][4] = {};

    // global load assignment
    int arow = tid >> 2;                 // 0..63 (+64 for second half)
    int acol = (tid & 3) * 4;            // 0,4,8,12
    int brow = tid >> 4;                 // 0..15
    int bcol = (tid & 15) * 4;           // 0..60

    const float* Ag = A + (size_t)(bm + arow) * K + acol;
    const float* Bg = B + (size_t)brow * Nn + bn + bcol;

    int niter = K / BKg;

    float4 a0v, a1v, bv;
    a0v = *(const float4*)Ag;
    a1v = *(const float4*)(Ag + (size_t)64 * K);
    bv  = *(const float4*)Bg;

    // store tile 0 into buffer 0
    {
        uint4 u0 = {f2tf32(a0v.x), f2tf32(a0v.y), f2tf32(a0v.z), f2tf32(a0v.w)};
        uint4 u1 = {f2tf32(a1v.x), f2tf32(a1v.y), f2tf32(a1v.z), f2tf32(a1v.w)};
        uint4 ub = {f2tf32(bv.x),  f2tf32(bv.y),  f2tf32(bv.z),  f2tf32(bv.w)};
        *(uint4*)&As[0][arow][acol]      = u0;
        *(uint4*)&As[0][arow + 64][acol] = u1;
        *(uint4*)&Bs[0][brow][bcol]      = ub;
    }
    __syncthreads();

    for (int it = 0; it < niter; it++) {
        int buf = it & 1;
        if (it + 1 < niter) {
            const float* Ap = Ag + (size_t)(it + 1) * BKg;
            a0v = *(const float4*)Ap;
            a1v = *(const float4*)(Ap + (size_t)64 * K);
            bv  = *(const float4*)(Bg + (size_t)(it + 1) * BKg * Nn);
        }
#pragma unroll
        for (int ks = 0; ks < 2; ks++) {
            int k0 = ks * 8;
            uint32_t af[2][4];
            uint32_t bf[4][2];
#pragma unroll
            for (int mt = 0; mt < 2; mt++) {
                int mb = wm + mt * 16;
                af[mt][0] = As[buf][mb + r][k0 + cq];
                af[mt][1] = As[buf][mb + r + 8][k0 + cq];
                af[mt][2] = As[buf][mb + r][k0 + cq + 4];
                af[mt][3] = As[buf][mb + r + 8][k0 + cq + 4];
            }
#pragma unroll
            for (int nt = 0; nt < 4; nt++) {
                int nb = wn + nt * 8;
                bf[nt][0] = Bs[buf][k0 + cq][nb + r];
                bf[nt][1] = Bs[buf][k0 + cq + 4][nb + r];
            }
#pragma unroll
            for (int mt = 0; mt < 2; mt++)
#pragma unroll
                for (int nt = 0; nt < 4; nt++) {
                    asm volatile(
                        "mma.sync.aligned.m16n8k8.row.col.f32.tf32.tf32.f32 "
                        "{%0,%1,%2,%3}, {%4,%5,%6,%7}, {%8,%9}, {%0,%1,%2,%3};"
                        : "+f"(acc[mt][nt][0]), "+f"(acc[mt][nt][1]),
                          "+f"(acc[mt][nt][2]), "+f"(acc[mt][nt][3])
                        : "r"(af[mt][0]), "r"(af[mt][1]), "r"(af[mt][2]), "r"(af[mt][3]),
                          "r"(bf[nt][0]), "r"(bf[nt][1]));
                }
        }
        if (it + 1 < niter) {
            uint4 u0 = {f2tf32(a0v.x), f2tf32(a0v.y), f2tf32(a0v.z), f2tf32(a0v.w)};
            uint4 u1 = {f2tf32(a1v.x), f2tf32(a1v.y), f2tf32(a1v.z), f2tf32(a1v.w)};
            uint4 ub = {f2tf32(bv.x),  f2tf32(bv.y),  f2tf32(bv.z),  f2tf32(bv.w)};
            int nb2 = buf ^ 1;
            *(uint4*)&As[nb2][arow][acol]      = u0;
            *(uint4*)&As[nb2][arow + 64][acol] = u1;
            *(uint4*)&Bs[nb2][brow][bcol]      = ub;
            __syncthreads();
        }
    }

    // epilogue
#pragma unroll
    for (int mt = 0; mt < 2; mt++) {
#pragma unroll
        for (int nt = 0; nt < 4; nt++) {
            int row0 = bm + wm + mt * 16 + r;
            int col  = bn + wn + nt * 8 + 2 * cq;
            float v[4] = {acc[mt][nt][0], acc[mt][nt][1], acc[mt][nt][2], acc[mt][nt][3]};
            if (BIAS) {
                float b0 = bias[col], b1 = bias[col + 1];
                v[0] += b0; v[1] += b1; v[2] += b0; v[3] += b1;
            }
            if (GELU) {
#pragma unroll
                for (int q = 0; q < 4; q++)
                    v[q] = v[q] * 0.5f * (1.0f + erff(v[q] * 0.70710678118654752f));
            }
            if (RES) {
                const float* r0 = Res + (size_t)row0 * Nn + col;
                const float* r1 = Res + (size_t)(row0 + 8) * Nn + col;
                v[0] += r0[0]; v[1] += r0[1]; v[2] += r1[0]; v[3] += r1[1];
            }
            *(float2*)(C + (size_t)row0 * Nn + col)       = make_float2(v[0], v[1]);
            *(float2*)(C + (size_t)(row0 + 8) * Nn + col) = make_float2(v[2], v[3]);
        }
    }
}

// ---------------- 5) attention: one block per (n, head) ----------------
__global__ void attn_kernel(const float* __restrict__ qkv, float* __restrict__ out) {
    int nb = blockIdx.x;
    int n = nb / HEADS, h = nb % HEADS;
    __shared__ float q[PP][DHEAD + 1];
    __shared__ float k[PP][DHEAD + 1];
    __shared__ float v[PP][DHEAD + 1];
    __shared__ float pr[PP][PP + 1];
    int t = threadIdx.x;
#pragma unroll
    for (int i = 0; i < PP; i++) {
        const float* base = qkv + (size_t)(n * PP + i) * (3 * OUTC) + h * DHEAD;
        q[i][t] = base[t];
        k[i][t] = base[OUTC + t];
        v[i][t] = base[2 * OUTC + t];
    }
    __syncthreads();
    if (t < PP * PP) {
        int i = t / PP, j = t % PP;
        float s = 0.0f;
#pragma unroll
        for (int d = 0; d < DHEAD; d++) s += q[i][d] * k[j][d];
        pr[i][j] = s * 0.125f;
    }
    __syncthreads();
    if (t < PP) {
        float mx = -3.4e38f;
#pragma unroll
        for (int j = 0; j < PP; j++) mx = fmaxf(mx, pr[t][j]);
        float sm = 0.0f;
#pragma unroll
        for (int j = 0; j < PP; j++) { float e = expf(pr[t][j] - mx); pr[t][j] = e; sm += e; }
        float inv = 1.0f / sm;
#pragma unroll
        for (int j = 0; j < PP; j++) pr[t][j] *= inv;
    }
    __syncthreads();
#pragma unroll
    for (int i = 0; i < PP; i++) {
        float o = 0.0f;
#pragma unroll
        for (int j = 0; j < PP; j++) o += pr[i][j] * v[j][t];
        out[(size_t)(n * PP + i) * OUTC + h * DHEAD + t] = o;
    }
}

// ---------------- launcher ----------------
extern "C" void kernel_launch(void* const* d_in, const int* in_sizes, int n_in,
                              void* d_out, int out_size) {
    const float* sil    = (const float*)d_in[0];
    const float* pose   = (const float*)d_in[1];
    const int*   mins   = (const int*)  d_in[2];
    const float* ln0_g  = (const float*)d_in[4];
    const float* ln0_b  = (const float*)d_in[5];
    const float* We     = (const float*)d_in[6];
    const float* be     = (const float*)d_in[7];
    const float* ln1_g  = (const float*)d_in[8];
    const float* ln1_b  = (const float*)d_in[9];
    const float* ln_a_g = (const float*)d_in[10];
    const float* ln_a_b = (const float*)d_in[11];
    const float* Wqkv   = (const float*)d_in[12];
    const float* Wo     = (const float*)d_in[13];
    const float* bo     = (const float*)d_in[14];
    const float* ln_f_g = (const float*)d_in[15];
    const float* ln_f_b = (const float*)d_in[16];
    const float* W1     = (const float*)d_in[17];
    const float* b1     = (const float*)d_in[18];
    const float* W2     = (const float*)d_in[19];
    const float* b2     = (const float*)d_in[20];
    float* out = (float*)d_out;

    float *X0, *Xn, *fuse, *qkv, *ao, *ff;
    cudaGetSymbolAddress((void**)&X0,   g_X0);
    cudaGetSymbolAddress((void**)&Xn,   g_Xn);
    cudaGetSymbolAddress((void**)&fuse, g_fuse);
    cudaGetSymbolAddress((void**)&qkv,  g_qkv);
    cudaGetSymbolAddress((void**)&ao,   g_ao);
    cudaGetSymbolAddress((void**)&ff,   g_ff);

    // Stage 1: fuse features
    {
        int tot = NB * PP * CC * MAXH;
        pool_kernel<<<(tot + 255) / 256, 256>>>(sil, mins, X0);
    }
    {
        int tot = NB * PP * POSEC * 2;
        pose_kernel<<<(tot + 255) / 256, 256>>>(pose, X0);
    }

    // Stage 2: LN0 -> embed GEMM -> LN1
    ln_kernel<FUSED><<<TOK, 256>>>(X0, Xn, ln0_g, ln0_b);
    gemm_tf32<true, false, false><<<dim3(OUTC / BNg, TOK / BMg), 256>>>(
        Xn, We, be, nullptr, fuse, TOK, OUTC, FUSED);
    ln_kernel<OUTC><<<TOK, 256>>>(fuse, fuse, ln1_g, ln1_b);

    // Stage 3: transformer layers
    for (int l = 0; l < DEPTH; l++) {
        ln_kernel<OUTC><<<TOK, 256>>>(fuse, Xn, ln_a_g + l * OUTC, ln_a_b + l * OUTC);
        gemm_tf32<false, false, false><<<dim3(3 * OUTC / BNg, TOK / BMg), 256>>>(
            Xn, Wqkv + (size_t)l * OUTC * 3 * OUTC, nullptr, nullptr, qkv,
            TOK, 3 * OUTC, OUTC);
        attn_kernel<<<NB * HEADS, 64>>>(qkv, ao);
        gemm_tf32<true, true, false><<<dim3(OUTC / BNg, TOK / BMg), 256>>>(
            ao, Wo + (size_t)l * OUTC * OUTC, bo + l * OUTC, fuse, fuse,
            TOK, OUTC, OUTC);
        ln_kernel<OUTC><<<TOK, 256>>>(fuse, Xn, ln_f_g + l * OUTC, ln_f_b + l * OUTC);
        gemm_tf32<true, false, true><<<dim3(FFH / BNg, TOK / BMg), 256>>>(
            Xn, W1 + (size_t)l * OUTC * FFH, b1 + l * FFH, nullptr, ff,
            TOK, FFH, OUTC);
        float* outp = (l == DEPTH - 1) ? out : fuse;
        gemm_tf32<true, true, false><<<dim3(OUTC / BNg, TOK / BMg), 256>>>(
            ff, W2 + (size_t)l * FFH * OUTC, b2 + l * OUTC, fuse, outp,
            TOK, OUTC, FFH);
    }
}

// round 6
// speedup vs baseline: 2.5586x; 1.6410x over previous
#include <cuda_runtime.h>
#include <cuda_bf16.h>
#include <math.h>
#include <stdint.h>

// ---------------- problem constants ----------------
#define NB     256
#define CC     128
#define HH     77
#define WW     44
#define PP     7
#define MAXH   11
#define POSEC  256
#define VV     17
#define OUTC   512
#define DEPTH  4
#define HEADS  8
#define DHEAD  64
#define FFH    1024
#define FUSED  1920          // C*MAX_H + POSE_C*2 = 1408 + 512
#define TOK    (NB*PP)       // 1792

// ---------------- scratch (static device memory; no allocation) ----------------
__device__ float g_X0[TOK * FUSED];
__device__ float g_Xn[TOK * FUSED];
__device__ float g_fuse[TOK * OUTC];
__device__ float g_qkv[TOK * 3 * OUTC];
__device__ float g_ao[TOK * OUTC];
__device__ float g_ff[TOK * FFH];

// ---------------- 1) silhouette pooling ----------------
__global__ void pool_kernel(const float* __restrict__ sil, const int* __restrict__ mins,
                            float* __restrict__ X0) {
    int idx = blockIdx.x * blockDim.x + threadIdx.x;
    const int total = NB * PP * CC * MAXH;
    if (idx >= total) return;
    int hl = idx % MAXH;
    int c  = (idx / MAXH) % CC;
    int p  = (idx / (MAXH * CC)) % PP;
    int n  = idx / (MAXH * CC * PP);
    int start = mins[p * NB + n];
    start = min(max(start, 0), HH - MAXH);
    int h = start + hl;
    const float4* row = (const float4*)(sil + (((size_t)n * CC + c) * HH + h) * WW);
    float s = 0.0f, mx = -3.4e38f;
#pragma unroll
    for (int w = 0; w < WW / 4; w++) {
        float4 v = row[w];
        s += v.x + v.y + v.z + v.w;
        mx = fmaxf(mx, fmaxf(fmaxf(v.x, v.y), fmaxf(v.z, v.w)));
    }
    X0[((size_t)(n * PP + p)) * FUSED + c * MAXH + hl] = s * (1.0f / WW) + mx;
}

// ---------------- 2) pose binning + leaky relu ----------------
__global__ void pose_kernel(const float* __restrict__ pose, float* __restrict__ X0) {
    int idx = blockIdx.x * blockDim.x + threadIdx.x;
    const int total = NB * PP * POSEC * 2;
    if (idx >= total) return;
    int b  = idx & 1;
    int pc = (idx >> 1) & (POSEC - 1);
    int p  = (idx >> 9) % PP;
    int n  = idx / (PP * POSEC * 2);
    const float* pp = pose + ((size_t)n * POSEC + pc) * VV;
    float v;
    if (p == 0) {
        v = (b == 0) ? (pp[0] + pp[1] + pp[2]) * (1.0f / 3.0f)
                     : (pp[2] + pp[3] + pp[4]) * (1.0f / 3.0f);
    } else {
        v = pp[3 + 2 * p + b];
    }
    v = (v >= 0.0f) ? v : 0.01f * v;
    X0[((size_t)(n * PP + p)) * FUSED + CC * MAXH + pc * 2 + b] = v;
}

// ---------------- 3) LayerNorm (block per row) ----------------
template <int D>
__global__ void ln_kernel(const float* __restrict__ X, float* __restrict__ Y,
                          const float* __restrict__ g, const float* __restrict__ b) {
    constexpr int NT = 256;
    constexpr int NE = (D + NT - 1) / NT;
    int row = blockIdx.x;
    const float* x = X + (size_t)row * D;
    float* y = Y + (size_t)row * D;
    int t = threadIdx.x;
    float vals[NE];
    float s = 0.0f, s2 = 0.0f;
#pragma unroll
    for (int e = 0; e < NE; e++) {
        int i = t + e * NT;
        float v = (i < D) ? x[i] : 0.0f;
        vals[e] = v;
        s += v; s2 += v * v;
    }
#pragma unroll
    for (int o = 16; o > 0; o >>= 1) {
        s  += __shfl_xor_sync(0xFFFFFFFFu, s, o);
        s2 += __shfl_xor_sync(0xFFFFFFFFu, s2, o);
    }
    __shared__ float sh[20];
    int wid = t >> 5, lid = t & 31;
    if (lid == 0) { sh[wid] = s; sh[8 + wid] = s2; }
    __syncthreads();
    if (t == 0) {
        float ts = 0.0f, ts2 = 0.0f;
#pragma unroll
        for (int w = 0; w < NT / 32; w++) { ts += sh[w]; ts2 += sh[8 + w]; }
        float m = ts / D;
        float var = ts2 / D - m * m;
        sh[16] = m;
        sh[17] = rsqrtf(var + 1e-5f);
    }
    __syncthreads();
    float m = sh[16], r = sh[17];
#pragma unroll
    for (int e = 0; e < NE; e++) {
        int i = t + e * NT;
        if (i < D) y[i] = (vals[e] - m) * r * g[i] + b[i];
    }
}

// ---------------- 4) tf32 tensor-core GEMM, cp.async 2-stage pipeline ----------------
// BM=64, BN=64, BK=32, 128 threads (4 warps 2x2, warp tile 32x32).
// Requires M%64==0, N%64==0, K%32==0 (true for all calls here).
#define BMg 64
#define BNg 64
#define BKg 32
#define ASTR 36   // BK+4: A frag banks = 4r+cq, conflict-free
#define BSTR 72   // BN+8: B frag banks = 8cq+r, conflict-free

__device__ __forceinline__ uint32_t f2tf32(float f) {
    uint32_t u;
    asm("cvt.rna.tf32.f32 %0, %1;" : "=r"(u) : "f"(f));
    return u;
}

#define CP16(smem_u32, gptr) \
    asm volatile("cp.async.cg.shared.global [%0], [%1], 16;" :: "r"(smem_u32), "l"(gptr))

template <bool BIAS, bool RES, bool GELU>
__global__ __launch_bounds__(128, 4)
void gemm_tf32(const float* __restrict__ A, const float* __restrict__ B,
               const float* __restrict__ bias, const float* __restrict__ Res,
               float* __restrict__ C, int M, int Nn, int K) {
    __shared__ float As[2][BMg][ASTR];   // 18,432 B
    __shared__ float Bs[2][BKg][BSTR];   // 18,432 B

    int tid = threadIdx.x;
    int bm = blockIdx.y * BMg, bn = blockIdx.x * BNg;
    int w = tid >> 5, lane = tid & 31;
    int wm = (w & 1) * 32, wn = (w >> 1) * 32;
    int r = lane >> 2, cq = lane & 3;

    float acc[2][4][4] = {};

    // copy assignments (coalesced 16B chunks)
    int a_row0 = tid >> 3;           // + j*16
    int a_col  = (tid & 7) * 4;
    int b_row0 = tid >> 4;           // + j*8
    int b_col  = (tid & 15) * 4;

    int niter = K / BKg;

    // precompute smem store addresses
    uint32_t a_sm[2][4], b_sm[2][4];
#pragma unroll
    for (int s = 0; s < 2; s++)
#pragma unroll
        for (int j = 0; j < 4; j++) {
            a_sm[s][j] = (uint32_t)__cvta_generic_to_shared(&As[s][a_row0 + j * 16][a_col]);
            b_sm[s][j] = (uint32_t)__cvta_generic_to_shared(&Bs[s][b_row0 + j * 8][b_col]);
        }

    // prologue: issue tile 0 -> stage 0
    {
#pragma unroll
        for (int j = 0; j < 4; j++)
            CP16(a_sm[0][j], A + (size_t)(bm + a_row0 + j * 16) * K + a_col);
#pragma unroll
        for (int j = 0; j < 4; j++)
            CP16(b_sm[0][j], B + (size_t)(b_row0 + j * 8) * Nn + bn + b_col);
        asm volatile("cp.async.commit_group;");
    }

    for (int it = 0; it < niter; it++) {
        int buf = it & 1;
        if (it + 1 < niter) {
            int s = buf ^ 1;
            int kt = (it + 1) * BKg;
#pragma unroll
            for (int j = 0; j < 4; j++)
                CP16(a_sm[s][j], A + (size_t)(bm + a_row0 + j * 16) * K + kt + a_col);
#pragma unroll
            for (int j = 0; j < 4; j++)
                CP16(b_sm[s][j], B + (size_t)(kt + b_row0 + j * 8) * Nn + bn + b_col);
            asm volatile("cp.async.commit_group;");
            asm volatile("cp.async.wait_group 1;");
        } else {
            asm volatile("cp.async.wait_group 0;");
        }
        __syncthreads();

#pragma unroll
        for (int ks = 0; ks < 4; ks++) {
            int k0 = ks * 8;
            uint32_t af[2][4];
            uint32_t bf[4][2];
#pragma unroll
            for (int mt = 0; mt < 2; mt++) {
                int mb = wm + mt * 16;
                af[mt][0] = f2tf32(As[buf][mb + r][k0 + cq]);
                af[mt][1] = f2tf32(As[buf][mb + r + 8][k0 + cq]);
                af[mt][2] = f2tf32(As[buf][mb + r][k0 + cq + 4]);
                af[mt][3] = f2tf32(As[buf][mb + r + 8][k0 + cq + 4]);
            }
#pragma unroll
            for (int nt = 0; nt < 4; nt++) {
                int nb = wn + nt * 8;
                bf[nt][0] = f2tf32(Bs[buf][k0 + cq][nb + r]);
                bf[nt][1] = f2tf32(Bs[buf][k0 + cq + 4][nb + r]);
            }
#pragma unroll
            for (int mt = 0; mt < 2; mt++)
#pragma unroll
                for (int nt = 0; nt < 4; nt++) {
                    asm volatile(
                        "mma.sync.aligned.m16n8k8.row.col.f32.tf32.tf32.f32 "
                        "{%0,%1,%2,%3}, {%4,%5,%6,%7}, {%8,%9}, {%0,%1,%2,%3};"
                        : "+f"(acc[mt][nt][0]), "+f"(acc[mt][nt][1]),
                          "+f"(acc[mt][nt][2]), "+f"(acc[mt][nt][3])
                        : "r"(af[mt][0]), "r"(af[mt][1]), "r"(af[mt][2]), "r"(af[mt][3]),
                          "r"(bf[nt][0]), "r"(bf[nt][1]));
                }
        }
        __syncthreads();
    }

    // epilogue
#pragma unroll
    for (int mt = 0; mt < 2; mt++) {
#pragma unroll
        for (int nt = 0; nt < 4; nt++) {
            int row0 = bm + wm + mt * 16 + r;
            int col  = bn + wn + nt * 8 + 2 * cq;
            float v[4] = {acc[mt][nt][0], acc[mt][nt][1], acc[mt][nt][2], acc[mt][nt][3]};
            if (BIAS) {
                float b0 = bias[col], b1 = bias[col + 1];
                v[0] += b0; v[1] += b1; v[2] += b0; v[3] += b1;
            }
            if (GELU) {
#pragma unroll
                for (int q = 0; q < 4; q++)
                    v[q] = v[q] * 0.5f * (1.0f + erff(v[q] * 0.70710678118654752f));
            }
            if (RES) {
                const float* r0 = Res + (size_t)row0 * Nn + col;
                const float* r1 = Res + (size_t)(row0 + 8) * Nn + col;
                v[0] += r0[0]; v[1] += r0[1]; v[2] += r1[0]; v[3] += r1[1];
            }
            *(float2*)(C + (size_t)row0 * Nn + col)       = make_float2(v[0], v[1]);
            *(float2*)(C + (size_t)(row0 + 8) * Nn + col) = make_float2(v[2], v[3]);
        }
    }
}

// ---------------- 5) attention: one block per (n, head) ----------------
__global__ void attn_kernel(const float* __restrict__ qkv, float* __restrict__ out) {
    int nb = blockIdx.x;
    int n = nb / HEADS, h = nb % HEADS;
    __shared__ float q[PP][DHEAD + 1];
    __shared__ float k[PP][DHEAD + 1];
    __shared__ float v[PP][DHEAD + 1];
    __shared__ float pr[PP][PP + 1];
    int t = threadIdx.x;
#pragma unroll
    for (int i = 0; i < PP; i++) {
        const float* base = qkv + (size_t)(n * PP + i) * (3 * OUTC) + h * DHEAD;
        q[i][t] = base[t];
        k[i][t] = base[OUTC + t];
        v[i][t] = base[2 * OUTC + t];
    }
    __syncthreads();
    if (t < PP * PP) {
        int i = t / PP, j = t % PP;
        float s = 0.0f;
#pragma unroll
        for (int d = 0; d < DHEAD; d++) s += q[i][d] * k[j][d];
        pr[i][j] = s * 0.125f;
    }
    __syncthreads();
    if (t < PP) {
        float mx = -3.4e38f;
#pragma unroll
        for (int j = 0; j < PP; j++) mx = fmaxf(mx, pr[t][j]);
        float sm = 0.0f;
#pragma unroll
        for (int j = 0; j < PP; j++) { float e = expf(pr[t][j] - mx); pr[t][j] = e; sm += e; }
        float inv = 1.0f / sm;
#pragma unroll
        for (int j = 0; j < PP; j++) pr[t][j] *= inv;
    }
    __syncthreads();
#pragma unroll
    for (int i = 0; i < PP; i++) {
        float o = 0.0f;
#pragma unroll
        for (int j = 0; j < PP; j++) o += pr[i][j] * v[j][t];
        out[(size_t)(n * PP + i) * OUTC + h * DHEAD + t] = o;
    }
}

// ---------------- launcher ----------------
extern "C" void kernel_launch(void* const* d_in, const int* in_sizes, int n_in,
                              void* d_out, int out_size) {
    const float* sil    = (const float*)d_in[0];
    const float* pose   = (const float*)d_in[1];
    const int*   mins   = (const int*)  d_in[2];
    const float* ln0_g  = (const float*)d_in[4];
    const float* ln0_b  = (const float*)d_in[5];
    const float* We     = (const float*)d_in[6];
    const float* be     = (const float*)d_in[7];
    const float* ln1_g  = (const float*)d_in[8];
    const float* ln1_b  = (const float*)d_in[9];
    const float* ln_a_g = (const float*)d_in[10];
    const float* ln_a_b = (const float*)d_in[11];
    const float* Wqkv   = (const float*)d_in[12];
    const float* Wo     = (const float*)d_in[13];
    const float* bo     = (const float*)d_in[14];
    const float* ln_f_g = (const float*)d_in[15];
    const float* ln_f_b = (const float*)d_in[16];
    const float* W1     = (const float*)d_in[17];
    const float* b1     = (const float*)d_in[18];
    const float* W2     = (const float*)d_in[19];
    const float* b2     = (const float*)d_in[20];
    float* out = (float*)d_out;

    float *X0, *Xn, *fuse, *qkv, *ao, *ff;
    cudaGetSymbolAddress((void**)&X0,   g_X0);
    cudaGetSymbolAddress((void**)&Xn,   g_Xn);
    cudaGetSymbolAddress((void**)&fuse, g_fuse);
    cudaGetSymbolAddress((void**)&qkv,  g_qkv);
    cudaGetSymbolAddress((void**)&ao,   g_ao);
    cudaGetSymbolAddress((void**)&ff,   g_ff);

    // Stage 1: fuse features
    {
        int tot = NB * PP * CC * MAXH;
        pool_kernel<<<(tot + 255) / 256, 256>>>(sil, mins, X0);
    }
    {
        int tot = NB * PP * POSEC * 2;
        pose_kernel<<<(tot + 255) / 256, 256>>>(pose, X0);
    }

    // Stage 2: LN0 -> embed GEMM -> LN1
    ln_kernel<FUSED><<<TOK, 256>>>(X0, Xn, ln0_g, ln0_b);
    gemm_tf32<true, false, false><<<dim3(OUTC / BNg, TOK / BMg), 128>>>(
        Xn, We, be, nullptr, fuse, TOK, OUTC, FUSED);
    ln_kernel<OUTC><<<TOK, 256>>>(fuse, fuse, ln1_g, ln1_b);

    // Stage 3: transformer layers
    for (int l = 0; l < DEPTH; l++) {
        ln_kernel<OUTC><<<TOK, 256>>>(fuse, Xn, ln_a_g + l * OUTC, ln_a_b + l * OUTC);
        gemm_tf32<false, false, false><<<dim3(3 * OUTC / BNg, TOK / BMg), 128>>>(
            Xn, Wqkv + (size_t)l * OUTC * 3 * OUTC, nullptr, nullptr, qkv,
            TOK, 3 * OUTC, OUTC);
        attn_kernel<<<NB * HEADS, 64>>>(qkv, ao);
        gemm_tf32<true, true, false><<<dim3(OUTC / BNg, TOK / BMg), 128>>>(
            ao, Wo + (size_t)l * OUTC * OUTC, bo + l * OUTC, fuse, fuse,
            TOK, OUTC, OUTC);
        ln_kernel<OUTC><<<TOK, 256>>>(fuse, Xn, ln_f_g + l * OUTC, ln_f_b + l * OUTC);
        gemm_tf32<true, false, true><<<dim3(FFH / BNg, TOK / BMg), 128>>>(
            Xn, W1 + (size_t)l * OUTC * FFH, b1 + l * FFH, nullptr, ff,
            TOK, FFH, OUTC);
        float* outp = (l == DEPTH - 1) ? out : fuse;
        gemm_tf32<true, true, false><<<dim3(OUTC / BNg, TOK / BMg), 128>>>(
            ff, W2 + (size_t)l * FFH * OUTC, b2 + l * OUTC, fuse, outp,
            TOK, OUTC, FFH);
    }
}